// round 3
// baseline (speedup 1.0000x reference)
#include <cuda_runtime.h>

// AllZeroDigitalFilter: time-varying FIR with per-sample linearly interpolated
// frame coefficients.
//   y[bb][t] = sum_{k=0..49} x[bb][t-k] * ( bL[n][k] + w*(bR[n][k]-bL[n][k]) )
//   n = t/80, w = (t%80)/80, bR = b[min(n+1, N-1)], x zero-padded on the left.
//
// Strategy: two-accumulator split  y = A0 + w*A1  with A0 = sum x*bL,
// A1 = sum x*d (d = bR-bL), so the interpolation weight is applied once per
// sample instead of once per tap. Register-blocked sliding x-window: each
// thread computes R=10 contiguous samples inside ONE frame, so each tap needs
// only 2 coefficient LDS (shared by all R samples) + 1 new x LDS, and 2R FMAs.

#define BATCH     8
#define N_FRAMES  3000
#define FPERIOD   80
#define T_LEN     (N_FRAMES * FPERIOD)   // 240000
#define TAPS      50
#define ORD       49

#define FPB       24                     // frames per block (divides 3000)
#define SPB       (FPB * FPERIOD)        // 1920 samples per block
#define R         10                     // samples per thread (divides 80)
#define TPF       (FPERIOD / R)          // 8 threads per frame
#define THREADS   (FPB * TPF)            // 192

__global__ __launch_bounds__(THREADS)
void azdf_kernel(const float* __restrict__ x,
                 const float* __restrict__ b,
                 float* __restrict__ y)
{
    __shared__ float sx[ORD + SPB];      // x[t0-49 .. t0+SPB-1], 1969 floats
    __shared__ float sbl[FPB * TAPS];    // left coeffs per frame
    __shared__ float sd [FPB * TAPS];    // right-left diff per frame

    const int tid = threadIdx.x;
    const int bb  = blockIdx.y;
    const int f0  = blockIdx.x * FPB;
    const int t0  = f0 * FPERIOD;

    const float* xb  = x + (size_t)bb * T_LEN;
    const float* bbp = b + (size_t)bb * N_FRAMES * TAPS;

    // --- stage x window (zero left pad) ---
    for (int i = tid; i < ORD + SPB; i += THREADS) {
        int g = t0 - ORD + i;
        sx[i] = (g >= 0) ? xb[g] : 0.0f;
    }
    // --- stage coefficients: bl and diff (with last-frame clamp -> d=0) ---
    for (int i = tid; i < FPB * TAPS; i += THREADS) {
        int f = i / TAPS;
        int k = i - f * TAPS;
        float bl = bbp[(f0 + f) * TAPS + k];
        int f1 = f0 + f + 1;
        if (f1 > N_FRAMES - 1) f1 = N_FRAMES - 1;
        float br = bbp[f1 * TAPS + k];
        sbl[i] = bl;
        sd[i]  = br - bl;
    }
    __syncthreads();

    const int fi  = tid / TPF;           // frame within block
    const int sub = tid - fi * TPF;      // thread within frame
    const int p0  = sub * R;             // first sample position in frame
    const int s   = fi * FPERIOD + p0;   // first sample offset in block
    const int off = s + ORD;             // index of sample s in sx at k=0

    float w[R], a0[R], a1[R];
    #pragma unroll
    for (int m = 0; m < R; m++) {
        w[m]  = sx[off + m];
        a0[m] = 0.0f;
        a1[m] = 0.0f;
    }

    const float* cbl = sbl + fi * TAPS;
    const float* cd  = sd  + fi * TAPS;

    #pragma unroll
    for (int k = 0; k < TAPS; k++) {
        float bl = cbl[k];
        float dd = cd[k];
        #pragma unroll
        for (int m = 0; m < R; m++) {
            a0[m] = fmaf(w[m], bl, a0[m]);
            a1[m] = fmaf(w[m], dd, a1[m]);
        }
        if (k < TAPS - 1) {
            // slide window down by one sample (renamed away when unrolled)
            #pragma unroll
            for (int m = R - 1; m > 0; m--) w[m] = w[m - 1];
            w[0] = sx[off - k - 1];
        }
    }

    float* yo = y + (size_t)bb * T_LEN + t0 + s;
    #pragma unroll
    for (int m = 0; m < R; m++) {
        float wt = (float)(p0 + m) * (1.0f / FPERIOD);
        yo[m] = fmaf(wt, a1[m], a0[m]);
    }
}

extern "C" void kernel_launch(void* const* d_in, const int* in_sizes, int n_in,
                              void* d_out, int out_size)
{
    const float* x = (const float*)d_in[0];
    const float* b = (const float*)d_in[1];
    // defensive: identify x by its element count (B*T vs B*N*(ORD+1))
    if (in_sizes[0] != BATCH * T_LEN) {
        const float* t = x; x = b; b = t;
    }
    dim3 grid(N_FRAMES / FPB, BATCH);
    azdf_kernel<<<grid, THREADS>>>(x, b, (float*)d_out);
}

// round 4
// speedup vs baseline: 1.5000x; 1.5000x over previous
#include <cuda_runtime.h>

// Time-varying FIR, y = A0 + w*A1 two-accumulator split.
//   y[bb][t] = sum_k x[t-k] * (bL[n][k] + w*(bR[n][k]-bL[n][k])), n=t/80, w=(t%80)/80
// j-form (ascending x): y[u] = sum_j sx[u+j] * c49[j], c49[j] = coeff[49-j].
// R=4 samples/thread, all shared loads 16B-vectorized, fine-grain grid.

#define BATCH     8
#define N_FRAMES  3000
#define FPERIOD   80
#define T_LEN     (N_FRAMES * FPERIOD)   // 240000
#define TAPS      50
#define ORD       49

#define FPB       8                      // frames per block (divides 3000)
#define SPB       (FPB * FPERIOD)        // 640 samples per block
#define R         4                      // samples per thread
#define TPF       (FPERIOD / R)          // 20 threads per frame
#define THREADS   (FPB * TPF)            // 160 = 5 warps

#define SX_LEN    (ORD + SPB)            // 689
#define SX_PAD    696                    // room for float4 over-read at j=48

__global__ __launch_bounds__(THREADS)
void azdf_kernel(const float* __restrict__ x,
                 const float* __restrict__ b,
                 float* __restrict__ y)
{
    __shared__ __align__(16) float sx[SX_PAD];
    // interleaved (c49[j], d49[j]) per frame: 100 floats per frame, 16B-aligned rows
    __shared__ __align__(16) float sc[FPB * TAPS * 2];

    const int tid = threadIdx.x;
    const int bb  = blockIdx.y;
    const int f0  = blockIdx.x * FPB;
    const int t0  = f0 * FPERIOD;

    const float* xb  = x + (size_t)bb * T_LEN;
    const float* bbp = b + (size_t)bb * N_FRAMES * TAPS;

    // --- stage x window: sx[i] = x[t0 - 49 + i], zero left pad ---
    #pragma unroll
    for (int i = tid; i < SX_LEN; i += THREADS) {
        int g = t0 - ORD + i;
        sx[i] = (g >= 0) ? xb[g] : 0.0f;
    }
    // --- stage coefficients reversed + diff: sc[f*100 + 2j] = bL[49-j], +1 = bR-bL ---
    #pragma unroll
    for (int i = tid; i < FPB * TAPS; i += THREADS) {
        int f = i / TAPS;
        int j = i - f * TAPS;
        int k = ORD - j;
        float bl = bbp[(f0 + f) * TAPS + k];
        int f1 = f0 + f + 1;
        if (f1 > N_FRAMES - 1) f1 = N_FRAMES - 1;
        float br = bbp[f1 * TAPS + k];
        sc[f * (2 * TAPS) + 2 * j]     = bl;
        sc[f * (2 * TAPS) + 2 * j + 1] = br - bl;
    }
    __syncthreads();

    const int fi  = tid / TPF;            // frame within block
    const int sub = tid - fi * TPF;       // thread within frame
    const int p0  = sub * R;              // phase of first sample in frame
    const int s   = fi * FPERIOD + p0;    // first sample offset in block (mult of 4)

    // initial window: w[m] = sx[s + m]
    float4 wv = *(const float4*)&sx[s];
    float w0 = wv.x, w1 = wv.y, w2 = wv.z, w3 = wv.w;
    float a00 = 0.f, a01 = 0.f, a02 = 0.f, a03 = 0.f;   // sum x*bL
    float a10 = 0.f, a11 = 0.f, a12 = 0.f, a13 = 0.f;   // sum x*diff

    const float4* cp = (const float4*)&sc[fi * (2 * TAPS)]; // 25 float4 = 2 taps each
    const float4* xq = (const float4*)&sx[s + R];           // prefetch groups

    float4 c, xp;
    #pragma unroll
    for (int j = 0; j < TAPS; j++) {
        if ((j & 1) == 0) c = cp[j >> 1];
        const float cb = (j & 1) ? c.z : c.x;
        const float cd = (j & 1) ? c.w : c.y;
        if ((j & 3) == 0) xp = xq[j >> 2];

        a00 = fmaf(w0, cb, a00);  a10 = fmaf(w0, cd, a10);
        a01 = fmaf(w1, cb, a01);  a11 = fmaf(w1, cd, a11);
        a02 = fmaf(w2, cb, a02);  a12 = fmaf(w2, cd, a12);
        a03 = fmaf(w3, cb, a03);  a13 = fmaf(w3, cd, a13);

        if (j < TAPS - 1) {
            const int ph = j & 3;
            float nx = (ph == 0) ? xp.x : (ph == 1) ? xp.y : (ph == 2) ? xp.z : xp.w;
            w0 = w1; w1 = w2; w2 = w3; w3 = nx;
        }
    }

    // epilogue: y = a0 + (phase/80) * a1 ; one STG.128
    const float inv = 1.0f / FPERIOD;
    float4 r;
    r.x = fmaf((float)(p0 + 0) * inv, a10, a00);
    r.y = fmaf((float)(p0 + 1) * inv, a11, a01);
    r.z = fmaf((float)(p0 + 2) * inv, a12, a02);
    r.w = fmaf((float)(p0 + 3) * inv, a13, a03);
    *(float4*)(y + (size_t)bb * T_LEN + t0 + s) = r;
}

extern "C" void kernel_launch(void* const* d_in, const int* in_sizes, int n_in,
                              void* d_out, int out_size)
{
    const float* x = (const float*)d_in[0];
    const float* b = (const float*)d_in[1];
    if (in_sizes[0] != BATCH * T_LEN) {   // defensive input-order check
        const float* t = x; x = b; b = t;
    }
    dim3 grid(N_FRAMES / FPB, BATCH);
    azdf_kernel<<<grid, THREADS>>>(x, b, (float*)d_out);
}